// round 2
// baseline (speedup 1.0000x reference)
#include <cuda_runtime.h>
#include <cuda_fp16.h>
#include <math.h>
#include <stdint.h>

#define Bb 2
#define Tt 2048
#define Ee 1024
#define Hh 16
#define Dd 64
#define BH 32
#define BT 4096  // B*T

static const size_t OUT_OFF = (size_t)Bb * Tt * Ee;  // 4194304 floats (out), then weights

// ---------------- scratch (device globals; no allocation allowed) ----------------
__device__ float g_q[BT * Ee];
__device__ float g_k[BT * Ee];
__device__ float g_v[BT * Ee];
__device__ float g_qr[BH * Tt * Dd];          // [bh, t, d]
__device__ float g_kr[BH * Tt * Dd];          // [bh, t, d]
__device__ float g_vt[BH * Dd * Tt];          // [bh, d, t]  (transposed for NT PV gemm)
__device__ float g_scores[(size_t)BH * Tt * Tt];  // 512MB: scores -> probs (fp16-quantized)
__device__ float g_attn[BT * Ee];             // [b, t, h*64+d]

// ---------------- generic batched NT GEMM: C = A (MxK) * B^T (B is NxK) + bias ----------------
template <int BM, int BN, int BK, int TM, int TN>
__global__ void __launch_bounds__((BM / TM) * (BN / TN))
gemm_nt(const float* __restrict__ A, const float* __restrict__ Bm,
        const float* __restrict__ bias, float* __restrict__ C,
        int M, int N, int K, int lda, int ldb, int ldc,
        long long sAz, long long sBz, long long sCz1, long long sCz2, int zdiv)
{
    constexpr int NT = (BM / TM) * (BN / TN);
    int z = blockIdx.z;
    A  += (long long)z * sAz;
    Bm += (long long)z * sBz;
    C  += (long long)(z / zdiv) * sCz1 + (long long)(z % zdiv) * sCz2;

    __shared__ float As[BK][BM];
    __shared__ float Bs[BK][BN];

    int tid = threadIdx.x;
    int tx = tid % (BN / TN);
    int ty = tid / (BN / TN);
    int row0 = blockIdx.y * BM;
    int col0 = blockIdx.x * BN;

    float acc[TM][TN];
#pragma unroll
    for (int i = 0; i < TM; i++)
#pragma unroll
        for (int j = 0; j < TN; j++) acc[i][j] = 0.0f;

    for (int k0 = 0; k0 < K; k0 += BK) {
#pragma unroll
        for (int off = tid * 4; off < BM * BK; off += NT * 4) {
            int r = off / BK, c = off % BK;
            float4 va = *(const float4*)&A[(size_t)(row0 + r) * lda + k0 + c];
            As[c + 0][r] = va.x; As[c + 1][r] = va.y;
            As[c + 2][r] = va.z; As[c + 3][r] = va.w;
        }
#pragma unroll
        for (int off = tid * 4; off < BN * BK; off += NT * 4) {
            int r = off / BK, c = off % BK;
            float4 vb = *(const float4*)&Bm[(size_t)(col0 + r) * ldb + k0 + c];
            Bs[c + 0][r] = vb.x; Bs[c + 1][r] = vb.y;
            Bs[c + 2][r] = vb.z; Bs[c + 3][r] = vb.w;
        }
        __syncthreads();
#pragma unroll
        for (int kk = 0; kk < BK; kk++) {
            float a[TM], b[TN];
#pragma unroll
            for (int i = 0; i < TM; i++) a[i] = As[kk][ty * TM + i];
#pragma unroll
            for (int j = 0; j < TN; j++) b[j] = Bs[kk][tx * TN + j];
#pragma unroll
            for (int i = 0; i < TM; i++)
#pragma unroll
                for (int j = 0; j < TN; j++) acc[i][j] = fmaf(a[i], b[j], acc[i][j]);
        }
        __syncthreads();
    }

#pragma unroll
    for (int i = 0; i < TM; i++) {
        int gr = row0 + ty * TM + i;
#pragma unroll
        for (int j = 0; j < TN; j++) {
            int gc = col0 + tx * TN + j;
            float cv = acc[i][j];
            if (bias) cv += bias[gc];
            C[(size_t)gr * ldc + gc] = cv;
        }
    }
}

// ---------------- prune (top-512 of 1024 per row) + head split + xPos ----------------
// mode 0: v  -> g_vt [bh, d, t]
// mode 1: q  -> scale 0.125, xPos (upscale)   -> [bh, t, d]
// mode 2: k  -> xPos (downscale)              -> [bh, t, d]
__global__ void __launch_bounds__(1024)
prune_transform(const float* __restrict__ X, float* __restrict__ out, int mode)
{
    int row = blockIdx.x;            // b*T + t
    int b = row >> 11;
    int t = row & 2047;
    int e = threadIdx.x;

    __shared__ float s[1024];
    __shared__ float vals[1024];

    float x = X[(size_t)row * 1024 + e];
    s[e] = x;
    __syncthreads();

    // bitonic ascending sort of a copy
    for (int k = 2; k <= 1024; k <<= 1) {
        for (int j = k >> 1; j > 0; j >>= 1) {
            int ixj = e ^ j;
            if (ixj > e) {
                float a = s[e], c = s[ixj];
                bool up = ((e & k) == 0);
                if ((a > c) == up) { s[e] = c; s[ixj] = a; }
            }
            __syncthreads();
        }
    }
    float thr = s[512];              // 512th largest value
    float m = (x >= thr) ? x : 0.0f;

    int h = e >> 6, d = e & 63;
    if (mode == 0) {
        out[((size_t)(b * 16 + h) * 64 + d) * 2048 + t] = m;
        return;
    }
    if (mode == 1) m *= 0.125f;      // D^-0.5
    vals[e] = m;
    __syncthreads();

    int i = d >> 1;
    float base = (2.0f * (float)i + 25.6f) / 89.6f;     // (2i + 0.4*Dh)/(1.4*Dh)
    float p = ((float)t - 1024.0f) / 512.0f;            // (t + min_pos)/SCALE_BASE
    if (mode == 2) p = -p;                              // downscale
    float sc = powf(base, p);
    float freq = powf(10000.0f, -(float)i / 32.0f);
    float ang = (float)t * freq;
    float sn = sinf(ang) * sc;
    float cs = cosf(ang) * sc;
    float partner = vals[e ^ 1];
    float o = (d & 1) ? (m * cs + partner * sn) : (m * cs - partner * sn);
    out[((size_t)(b * 16 + h) * 2048 + t) * 64 + d] = o;
}

// ---------------- row softmax + fp16 quantize; writes probs (in place) and d_out weights ----------------
__global__ void __launch_bounds__(256)
softmax_rows(float* __restrict__ scores, float* __restrict__ wout)
{
    int t = blockIdx.x;
    int bh = blockIdx.y;
    float* row = scores + ((size_t)bh * 2048 + t) * 2048;
    int tid = threadIdx.x;

    float v[8];
    float mx = -INFINITY;
#pragma unroll
    for (int i = 0; i < 8; i++) {
        v[i] = row[tid + i * 256];
        mx = fmaxf(mx, v[i]);
    }
    __shared__ float red[256];
    red[tid] = mx; __syncthreads();
    for (int s2 = 128; s2 > 0; s2 >>= 1) {
        if (tid < s2) red[tid] = fmaxf(red[tid], red[tid + s2]);
        __syncthreads();
    }
    mx = red[0];
    __syncthreads();

    float sm = 0.0f;
#pragma unroll
    for (int i = 0; i < 8; i++) { v[i] = expf(v[i] - mx); sm += v[i]; }
    red[tid] = sm; __syncthreads();
    for (int s2 = 128; s2 > 0; s2 >>= 1) {
        if (tid < s2) red[tid] += red[tid + s2];
        __syncthreads();
    }
    float inv = 1.0f / red[0];

    int b = bh >> 4, h = bh & 15;
    float* wrow = wout + ((size_t)(h * 2 + b) * 2048 + t) * 2048;
#pragma unroll
    for (int i = 0; i < 8; i++) {
        __half hh = __float2half(v[i] * inv);   // fp32 -> fp16 RN, matching .astype(float16)
        float f = __half2float(hh);
        row[tid + i * 256] = f;                 // probs for PV gemm
        wrow[tid + i * 256] = f;                // attn_weights output (upcast to fp32)
    }
}

extern "C" void kernel_launch(void* const* d_in, const int* in_sizes, int n_in,
                              void* d_out, int out_size)
{
    const float* query = (const float*)d_in[0];
    const float* key   = (const float*)d_in[1];
    const float* value = (const float*)d_in[2];
    const float* Wq = (const float*)d_in[3];
    const float* bq = (const float*)d_in[4];
    const float* Wk = (const float*)d_in[5];
    const float* bk = (const float*)d_in[6];
    const float* Wv = (const float*)d_in[7];
    const float* bv = (const float*)d_in[8];
    const float* Wo = (const float*)d_in[9];
    const float* bo = (const float*)d_in[10];
    float* out = (float*)d_out;

    float *qp, *kp, *vp, *qr, *kr, *vt, *sc, *at;
    cudaGetSymbolAddress((void**)&qp, g_q);
    cudaGetSymbolAddress((void**)&kp, g_k);
    cudaGetSymbolAddress((void**)&vp, g_v);
    cudaGetSymbolAddress((void**)&qr, g_qr);
    cudaGetSymbolAddress((void**)&kr, g_kr);
    cudaGetSymbolAddress((void**)&vt, g_vt);
    cudaGetSymbolAddress((void**)&sc, g_scores);
    cudaGetSymbolAddress((void**)&at, g_attn);

    const long long NOB = 1;  // no-batch zdiv
    // --- projections: [4096,1024] = X[4096,1024] @ W^T + b ---
    {
        dim3 grid(Ee / 128, BT / 128, 1);
        gemm_nt<128, 128, 16, 8, 8><<<grid, 256>>>(query, Wq, bq, qp,
            BT, Ee, Ee, Ee, Ee, Ee, 0, 0, 0, 0, (int)NOB);
        gemm_nt<128, 128, 16, 8, 8><<<grid, 256>>>(key, Wk, bk, kp,
            BT, Ee, Ee, Ee, Ee, Ee, 0, 0, 0, 0, (int)NOB);
        gemm_nt<128, 128, 16, 8, 8><<<grid, 256>>>(value, Wv, bv, vp,
            BT, Ee, Ee, Ee, Ee, Ee, 0, 0, 0, 0, (int)NOB);
    }

    // --- prune + split heads + xPos ---
    prune_transform<<<BT, 1024>>>(vp, vt, 0);
    prune_transform<<<BT, 1024>>>(qp, qr, 1);
    prune_transform<<<BT, 1024>>>(kp, kr, 2);

    // --- scores: per bh, S[2048,2048] = q_r @ k_r^T ---
    {
        dim3 grid(Tt / 128, Tt / 128, BH);
        gemm_nt<128, 128, 16, 8, 8><<<grid, 256>>>(qr, kr, nullptr, sc,
            Tt, Tt, Dd, Dd, Dd, Tt,
            (long long)Tt * Dd, (long long)Tt * Dd,
            0, (long long)Tt * Tt, 1 << 30);
    }

    // --- softmax + fp16 quantize; writes weights region of d_out ---
    {
        dim3 grid(Tt, BH);
        softmax_rows<<<grid, 256>>>(sc, out + OUT_OFF);
    }

    // --- PV: per bh, attn[2048,64] = probs @ v ; written straight into [B,T,E] layout ---
    {
        dim3 grid(Dd / 64, Tt / 64, BH);
        gemm_nt<64, 64, 16, 4, 4><<<grid, 256>>>(sc, vt, nullptr, at,
            Tt, Dd, Tt, Tt, Tt, Ee,
            (long long)Tt * Tt, (long long)Dd * Tt,
            (long long)Tt * Ee,     // per-b stride (z/16)
            (long long)Dd,          // per-h stride (z%16)
            16);
    }

    // --- output projection: out = attn @ Wo^T + bo ---
    {
        dim3 grid(Ee / 128, BT / 128, 1);
        gemm_nt<128, 128, 16, 8, 8><<<grid, 256>>>(at, Wo, bo, out,
            BT, Ee, Ee, Ee, Ee, Ee, 0, 0, 0, 0, (int)NOB);
    }
}